// round 8
// baseline (speedup 1.0000x reference)
#include <cuda_runtime.h>
#include <cstdint>
#include <cstddef>

#define N_TOKENS   16384
#define IN_F       1024
#define OUT_F      1024
#define BH         32
#define BW         32
#define NB         256
#define N_RB       (OUT_F / BH)   // 32
#define TOK_TILE   256
#define THREADS    256
#define SMAX       11             // W blocks per smem chunk (44KB)

__device__ int g_cnt[N_RB];
__device__ int g_blk[N_RB][NB];
__device__ int g_col[N_RB][NB];

__global__ void spmm_prep_kernel(const int* __restrict__ brow,
                                 const int* __restrict__ bcol) {
    int rb = threadIdx.x;
    if (rb >= N_RB) return;
    int c = 0;
    for (int b = 0; b < NB; ++b) {
        if (brow[b] == rb) { g_blk[rb][c] = b; g_col[rb][c] = bcol[b]; ++c; }
    }
    g_cnt[rb] = c;
}

// pack two floats into bf16x2: element with LOWER k index in the LOW half.
__device__ __forceinline__ unsigned pack_bf16(float hi, float lo) {
    unsigned d;
    asm("cvt.rn.bf16x2.f32 %0, %1, %2;" : "=r"(d) : "f"(hi), "f"(lo));
    return d;
}
__device__ __forceinline__ float bf_lo(unsigned r) { return __uint_as_float(r << 16); }
__device__ __forceinline__ float bf_hi(unsigned r) { return __uint_as_float(r & 0xffff0000u); }

__device__ __forceinline__ void mma_bf16(float* d, const unsigned* a, const unsigned* b) {
    asm volatile(
        "mma.sync.aligned.m16n8k16.row.col.f32.bf16.bf16.f32 "
        "{%0,%1,%2,%3}, {%4,%5,%6,%7}, {%8,%9}, {%0,%1,%2,%3};"
        : "+f"(d[0]), "+f"(d[1]), "+f"(d[2]), "+f"(d[3])
        : "r"(a[0]), "r"(a[1]), "r"(a[2]), "r"(a[3]), "r"(b[0]), "r"(b[1]));
}

// float4 covering phys cols 4c..4c+3 -> (main, residual) bf16x2 fragment regs.
__device__ __forceinline__ void split_bf16_pair(const float4& f,
                                                unsigned& m0, unsigned& m1,
                                                unsigned& r0, unsigned& r1) {
    m0 = pack_bf16(f.y, f.x);
    m1 = pack_bf16(f.w, f.z);
    r0 = pack_bf16(f.y - bf_hi(m0), f.x - bf_lo(m0));
    r1 = pack_bf16(f.w - bf_hi(m1), f.z - bf_lo(m1));
}

// CTA: 256 tokens x one 32-wide row-block. 8 independent warps (32 tok x 32 out).
// bf16x3 emulation (a_m*b_m + a_m*b_r + a_r*b_m). W staged in smem chunks of SMAX
// as pre-converted bf16 fragments; A software-pipelined with ping-pong LDG.128
// prefetch so L2 latency hides under the previous iteration's MMAs.
__global__ __launch_bounds__(THREADS, 2)
void spmm_main_kernel(const float* __restrict__ x,
                      const float* __restrict__ w,
                      const float* __restrict__ bias,
                      float* __restrict__ out) {
    // smB[li][s][nt][lane] = uint4{bm0, bm1, br0, br1}
    __shared__ alignas(16) uint4 smB[SMAX * 2 * 4 * 32];   // 44 KB

    const int rb   = blockIdx.y;
    const int tok0 = blockIdx.x * TOK_TILE;
    const int tid  = threadIdx.x;
    const int wid  = tid >> 5;
    const int lane = tid & 31;
    const int g    = lane >> 2;   // 0..7
    const int c    = lane & 3;    // 0..3

    const int cnt = g_cnt[rb];

    float acc[2][4][4];
#pragma unroll
    for (int mt = 0; mt < 2; ++mt)
#pragma unroll
        for (int nt = 0; nt < 4; ++nt)
#pragma unroll
            for (int r = 0; r < 4; ++r) acc[mt][nt][r] = 0.0f;

    const float* xw = x + (size_t)(tok0 + wid * 32) * IN_F;

    float4 qa[2][2][2], qb[2][2][2];   // [mt][rowhalf][s] ping-pong A buffers

    auto load_q = [&](float4 (&q)[2][2][2], int i) {
        const float* xb = xw + g_col[rb][i] * BW;
#pragma unroll
        for (int mt = 0; mt < 2; ++mt)
#pragma unroll
            for (int a = 0; a < 2; ++a)
#pragma unroll
                for (int s = 0; s < 2; ++s)
                    q[mt][a][s] = *(const float4*)
                        (xb + (size_t)(mt * 16 + 8 * a + g) * IN_F + 16 * s + 4 * c);
    };

    auto compute = [&](const float4 (&q)[2][2][2], int li) {
#pragma unroll
        for (int s = 0; s < 2; ++s) {
            unsigned am[2][4], ar[2][4];
#pragma unroll
            for (int mt = 0; mt < 2; ++mt) {
                split_bf16_pair(q[mt][0][s], am[mt][0], am[mt][2], ar[mt][0], ar[mt][2]);
                split_bf16_pair(q[mt][1][s], am[mt][1], am[mt][3], ar[mt][1], ar[mt][3]);
            }
#pragma unroll
            for (int nt = 0; nt < 4; ++nt) {
                const uint4 bv = smB[((li * 2 + s) * 4 + nt) * 32 + lane];
                const unsigned bm[2] = { bv.x, bv.y };
                const unsigned br[2] = { bv.z, bv.w };
#pragma unroll
                for (int mt = 0; mt < 2; ++mt) {
                    mma_bf16(acc[mt][nt], am[mt], bm);
                    mma_bf16(acc[mt][nt], am[mt], br);
                    mma_bf16(acc[mt][nt], ar[mt], bm);
                }
            }
        }
    };

    int done = 0;
    while (done < cnt) {
        const int n   = (cnt - done < SMAX) ? (cnt - done) : SMAX;
        const int end = done + n;

        __syncthreads();   // previous chunk fully consumed by all warps
        for (int ii = 0; ii < n; ++ii) {
            const float* wb = w + (size_t)g_blk[rb][done + ii] * (BH * BW);
            const int r = tid >> 3;          // W out-row 0..31
            const int j = tid & 7;           // float4 idx: cols 4j..4j+3
            const int s = j >> 2;
            const int cc = j & 3;
            const float4 f = *(const float4*)(wb + r * BW + j * 4);
            unsigned m0, m1, r0, r1;
            split_bf16_pair(f, m0, m1, r0, r1);
            const int nt = r >> 3;
            const int gg = r & 7;
            smB[((ii * 2 + s) * 4 + nt) * 32 + gg * 4 + cc] = make_uint4(m0, m1, r0, r1);
        }
        __syncthreads();

        // ---- ping-pong pipelined inner loop over this chunk ----
        int i = done;
        load_q(qa, i);
        while (true) {
            if (i + 1 < end) load_q(qb, i + 1);
            compute(qa, i - done);
            ++i;
            if (i >= end) break;
            if (i + 1 < end) load_q(qa, i + 1);
            compute(qb, i - done);
            ++i;
            if (i >= end) break;
        }
        done = end;
    }

    // ---- epilogue: add bias, store ----
    const float* bp = bias + rb * BH;
#pragma unroll
    for (int nt = 0; nt < 4; ++nt) {
        const float2 bv = *(const float2*)(bp + nt * 8 + 2 * c);
#pragma unroll
        for (int mt = 0; mt < 2; ++mt) {
            const int row0 = tok0 + wid * 32 + mt * 16 + g;
            float2 o0, o1;
            o0.x = acc[mt][nt][0] + bv.x;
            o0.y = acc[mt][nt][1] + bv.y;
            o1.x = acc[mt][nt][2] + bv.x;
            o1.y = acc[mt][nt][3] + bv.y;
            *(float2*)(out + (size_t)row0       * OUT_F + rb * BH + nt * 8 + 2 * c) = o0;
            *(float2*)(out + (size_t)(row0 + 8) * OUT_F + rb * BH + nt * 8 + 2 * c) = o1;
        }
    }
}

extern "C" void kernel_launch(void* const* d_in, const int* in_sizes, int n_in,
                              void* d_out, int out_size) {
    (void)in_sizes; (void)n_in; (void)out_size;
    const float* x    = (const float*)d_in[0];
    const float* w    = (const float*)d_in[1];
    const float* bias = (const float*)d_in[2];
    const int*   brow = (const int*)d_in[3];
    const int*   bcol = (const int*)d_in[4];
    float* out = (float*)d_out;

    spmm_prep_kernel<<<1, N_RB>>>(brow, bcol);
    dim3 grid(N_TOKENS / TOK_TILE, N_RB);
    spmm_main_kernel<<<grid, THREADS>>>(x, w, bias, out);
}

// round 9
// speedup vs baseline: 1.1106x; 1.1106x over previous
#include <cuda_runtime.h>
#include <cstdint>
#include <cstddef>

#define N_TOKENS   16384
#define IN_F       1024
#define OUT_F      1024
#define BH         32
#define BW         32
#define NB         256
#define N_RB       (OUT_F / BH)   // 32
#define TOK_TILE   256
#define THREADS    256
#define SMAX       8              // W blocks per smem chunk (32KB) -> 3 CTAs/SM

__device__ int g_cnt[N_RB];
__device__ int g_blk[N_RB][NB];
__device__ int g_col[N_RB][NB];

// 256 threads: stable parallel compaction (same order as the serial scan).
__global__ void spmm_prep_kernel(const int* __restrict__ brow,
                                 const int* __restrict__ bcol) {
    __shared__ int sr[NB];
    const int b = threadIdx.x;
    sr[b] = brow[b];
    __syncthreads();
    const int rb = sr[b];
    int pos = 0;
    for (int j = 0; j < b; ++j) pos += (sr[j] == rb);
    g_blk[rb][pos] = b;
    g_col[rb][pos] = bcol[b];
    if (b < N_RB) {
        int c = 0;
        for (int j = 0; j < NB; ++j) c += (sr[j] == b);
        g_cnt[b] = c;
    }
}

// pack two floats into bf16x2: element with LOWER k index in the LOW half.
__device__ __forceinline__ unsigned pack_bf16(float hi, float lo) {
    unsigned d;
    asm("cvt.rn.bf16x2.f32 %0, %1, %2;" : "=r"(d) : "f"(hi), "f"(lo));
    return d;
}
__device__ __forceinline__ float bf_lo(unsigned r) { return __uint_as_float(r << 16); }
__device__ __forceinline__ float bf_hi(unsigned r) { return __uint_as_float(r & 0xffff0000u); }

__device__ __forceinline__ void mma_bf16(float* d, const unsigned* a, const unsigned* b) {
    asm volatile(
        "mma.sync.aligned.m16n8k16.row.col.f32.bf16.bf16.f32 "
        "{%0,%1,%2,%3}, {%4,%5,%6,%7}, {%8,%9}, {%0,%1,%2,%3};"
        : "+f"(d[0]), "+f"(d[1]), "+f"(d[2]), "+f"(d[3])
        : "r"(a[0]), "r"(a[1]), "r"(a[2]), "r"(a[3]), "r"(b[0]), "r"(b[1]));
}

// float4 covering phys cols 4c..4c+3 -> (main, residual) bf16x2 fragment regs.
__device__ __forceinline__ void split_bf16_pair(const float4& f,
                                                unsigned& m0, unsigned& m1,
                                                unsigned& r0, unsigned& r1) {
    m0 = pack_bf16(f.y, f.x);
    m1 = pack_bf16(f.w, f.z);
    r0 = pack_bf16(f.y - bf_hi(m0), f.x - bf_lo(m0));
    r1 = pack_bf16(f.w - bf_hi(m1), f.z - bf_lo(m1));
}

// CTA: 256 tokens x one 32-wide row-block. 8 independent warps (32 tok x 32 out).
// bf16x3 emulation (a_m*b_m + a_m*b_r + a_r*b_m). W staged in smem chunks of SMAX
// as pre-converted bf16 fragments. A loaded with 8 batched LDG.128 per iter;
// latency hidden by 3-CTA occupancy (24 warps/SM) rather than in-thread ILP.
__global__ __launch_bounds__(THREADS, 3)
void spmm_main_kernel(const float* __restrict__ x,
                      const float* __restrict__ w,
                      const float* __restrict__ bias,
                      float* __restrict__ out) {
    // smB[li][s][nt][lane] = uint4{bm0, bm1, br0, br1}
    __shared__ alignas(16) uint4 smB[SMAX * 2 * 4 * 32];   // 32 KB

    const int rb   = blockIdx.y;
    const int tok0 = blockIdx.x * TOK_TILE;
    const int tid  = threadIdx.x;
    const int wid  = tid >> 5;
    const int lane = tid & 31;
    const int g    = lane >> 2;   // 0..7
    const int c    = lane & 3;    // 0..3

    const int cnt = g_cnt[rb];

    float acc[2][4][4];
#pragma unroll
    for (int mt = 0; mt < 2; ++mt)
#pragma unroll
        for (int nt = 0; nt < 4; ++nt)
#pragma unroll
            for (int r = 0; r < 4; ++r) acc[mt][nt][r] = 0.0f;

    const float* xw = x + (size_t)(tok0 + wid * 32) * IN_F;

    int done = 0;
    while (done < cnt) {
        const int n   = (cnt - done < SMAX) ? (cnt - done) : SMAX;
        const int end = done + n;

        __syncthreads();   // previous chunk fully consumed by all warps
        for (int ii = 0; ii < n; ++ii) {
            const float* wb = w + (size_t)g_blk[rb][done + ii] * (BH * BW);
            const int r = tid >> 3;          // W out-row 0..31
            const int j = tid & 7;           // float4 idx: cols 4j..4j+3
            const int s = j >> 2;
            const int cc = j & 3;
            const float4 f = *(const float4*)(wb + r * BW + j * 4);
            unsigned m0, m1, r0, r1;
            split_bf16_pair(f, m0, m1, r0, r1);
            const int nt = r >> 3;
            const int gg = r & 7;
            smB[((ii * 2 + s) * 4 + nt) * 32 + gg * 4 + cc] = make_uint4(m0, m1, r0, r1);
        }
        __syncthreads();

        for (int i = done; i < end; ++i) {
            const float* xb = xw + g_col[rb][i] * BW;
            const int li = i - done;

            // ---- A: 8 batched LDG.128 (MLP=8) ----
            float4 q[2][2][2];   // [mt][rowhalf a][s]
#pragma unroll
            for (int mt = 0; mt < 2; ++mt)
#pragma unroll
                for (int a = 0; a < 2; ++a)
#pragma unroll
                    for (int s = 0; s < 2; ++s)
                        q[mt][a][s] = *(const float4*)
                            (xb + (size_t)(mt * 16 + 8 * a + g) * IN_F + 16 * s + 4 * c);

#pragma unroll
            for (int s = 0; s < 2; ++s) {
                unsigned am[2][4], ar[2][4];
#pragma unroll
                for (int mt = 0; mt < 2; ++mt) {
                    split_bf16_pair(q[mt][0][s], am[mt][0], am[mt][2], ar[mt][0], ar[mt][2]);
                    split_bf16_pair(q[mt][1][s], am[mt][1], am[mt][3], ar[mt][1], ar[mt][3]);
                }
#pragma unroll
                for (int nt = 0; nt < 4; ++nt) {
                    const uint4 bv = smB[((li * 2 + s) * 4 + nt) * 32 + lane];
                    const unsigned bm[2] = { bv.x, bv.y };
                    const unsigned br[2] = { bv.z, bv.w };
#pragma unroll
                    for (int mt = 0; mt < 2; ++mt) {
                        mma_bf16(acc[mt][nt], am[mt], bm);
                        mma_bf16(acc[mt][nt], am[mt], br);
                        mma_bf16(acc[mt][nt], ar[mt], bm);
                    }
                }
            }
        }
        done = end;
    }

    // ---- epilogue: add bias, store ----
    const float* bp = bias + rb * BH;
#pragma unroll
    for (int nt = 0; nt < 4; ++nt) {
        const float2 bv = *(const float2*)(bp + nt * 8 + 2 * c);
#pragma unroll
        for (int mt = 0; mt < 2; ++mt) {
            const int row0 = tok0 + wid * 32 + mt * 16 + g;
            float2 o0, o1;
            o0.x = acc[mt][nt][0] + bv.x;
            o0.y = acc[mt][nt][1] + bv.y;
            o1.x = acc[mt][nt][2] + bv.x;
            o1.y = acc[mt][nt][3] + bv.y;
            *(float2*)(out + (size_t)row0       * OUT_F + rb * BH + nt * 8 + 2 * c) = o0;
            *(float2*)(out + (size_t)(row0 + 8) * OUT_F + rb * BH + nt * 8 + 2 * c) = o1;
        }
    }
}

extern "C" void kernel_launch(void* const* d_in, const int* in_sizes, int n_in,
                              void* d_out, int out_size) {
    (void)in_sizes; (void)n_in; (void)out_size;
    const float* x    = (const float*)d_in[0];
    const float* w    = (const float*)d_in[1];
    const float* bias = (const float*)d_in[2];
    const int*   brow = (const int*)d_in[3];
    const int*   bcol = (const int*)d_in[4];
    float* out = (float*)d_out;

    spmm_prep_kernel<<<1, NB>>>(brow, bcol);
    dim3 grid(N_TOKENS / TOK_TILE, N_RB);
    spmm_main_kernel<<<grid, THREADS>>>(x, w, bias, out);
}

// round 10
// speedup vs baseline: 1.1519x; 1.0373x over previous
#include <cuda_runtime.h>
#include <cstdint>
#include <cstddef>

#define N_TOKENS   16384
#define IN_F       1024
#define OUT_F      1024
#define BH         32
#define BW         32
#define NB         256
#define N_RB       (OUT_F / BH)   // 32
#define TOK_TILE   256
#define THREADS    256
#define SMAX       12             // W blocks per smem chunk (48KB static, exactly)

__device__ int g_cnt[N_RB];
__device__ int g_blk[N_RB][NB];
__device__ int g_col[N_RB][NB];

// 256 threads: stable parallel compaction (same order as a serial scan).
__global__ void spmm_prep_kernel(const int* __restrict__ brow,
                                 const int* __restrict__ bcol) {
    __shared__ int sr[NB];
    const int b = threadIdx.x;
    sr[b] = brow[b];
    __syncthreads();
    const int rb = sr[b];
    int pos = 0;
    for (int j = 0; j < b; ++j) pos += (sr[j] == rb);
    g_blk[rb][pos] = b;
    g_col[rb][pos] = bcol[b];
    if (b < N_RB) {
        int c = 0;
        for (int j = 0; j < NB; ++j) c += (sr[j] == b);
        g_cnt[b] = c;
    }
}

// pack two floats into bf16x2: element with LOWER k index in the LOW half.
__device__ __forceinline__ unsigned pack_bf16(float hi, float lo) {
    unsigned d;
    asm("cvt.rn.bf16x2.f32 %0, %1, %2;" : "=r"(d) : "f"(hi), "f"(lo));
    return d;
}
__device__ __forceinline__ float bf_lo(unsigned r) { return __uint_as_float(r << 16); }
__device__ __forceinline__ float bf_hi(unsigned r) { return __uint_as_float(r & 0xffff0000u); }

__device__ __forceinline__ void mma_bf16(float* d, const unsigned* a,
                                         unsigned b0, unsigned b1) {
    asm volatile(
        "mma.sync.aligned.m16n8k16.row.col.f32.bf16.bf16.f32 "
        "{%0,%1,%2,%3}, {%4,%5,%6,%7}, {%8,%9}, {%0,%1,%2,%3};"
        : "+f"(d[0]), "+f"(d[1]), "+f"(d[2]), "+f"(d[3])
        : "r"(a[0]), "r"(a[1]), "r"(a[2]), "r"(a[3]), "r"(b0), "r"(b1));
}

// float4 covering phys cols 4c..4c+3 -> (main, residual) bf16x2 fragment regs.
__device__ __forceinline__ void split_bf16_pair(const float4& f,
                                                unsigned& m0, unsigned& m1,
                                                unsigned& r0, unsigned& r1) {
    m0 = pack_bf16(f.y, f.x);
    m1 = pack_bf16(f.w, f.z);
    r0 = pack_bf16(f.y - bf_hi(m0), f.x - bf_lo(m0));
    r1 = pack_bf16(f.w - bf_hi(m1), f.z - bf_lo(m1));
}

// CTA: 256 tokens x one 32-wide row-block. 8 independent warps (32 tok x 32 out).
// bf16x3 emulation (a_m*b_m + a_m*b_r + a_r*b_m). W staged in smem chunks as
// pre-converted bf16 fragments. Anti-convoy: each warp walks the chunk's blocks
// in a rotated order so L1 bursts decorrelate. Anti-RAW: MMAs issued term-major
// (all 8 main*main across nt,mt before the residual terms).
__global__ __launch_bounds__(THREADS, 2)
void spmm_main_kernel(const float* __restrict__ x,
                      const float* __restrict__ w,
                      const float* __restrict__ bias,
                      float* __restrict__ out) {
    // smB[li][s][nt][lane] = uint4{bm0, bm1, br0, br1} ; 48 KB
    __shared__ alignas(16) uint4 smB[SMAX * 2 * 4 * 32];

    const int rb   = blockIdx.y;
    const int tok0 = blockIdx.x * TOK_TILE;
    const int tid  = threadIdx.x;
    const int wid  = tid >> 5;
    const int lane = tid & 31;
    const int g    = lane >> 2;   // 0..7
    const int c    = lane & 3;    // 0..3

    const int cnt = g_cnt[rb];

    float acc[2][4][4];
#pragma unroll
    for (int mt = 0; mt < 2; ++mt)
#pragma unroll
        for (int nt = 0; nt < 4; ++nt)
#pragma unroll
            for (int r = 0; r < 4; ++r) acc[mt][nt][r] = 0.0f;

    const float* xw = x + (size_t)(tok0 + wid * 32) * IN_F;

    int done = 0;
    while (done < cnt) {
        const int n = (cnt - done < SMAX) ? (cnt - done) : SMAX;

        __syncthreads();   // previous chunk fully consumed by all warps
        for (int ii = 0; ii < n; ++ii) {
            const float* wb = w + (size_t)g_blk[rb][done + ii] * (BH * BW);
            const int r = tid >> 3;          // W out-row 0..31
            const int j = tid & 7;           // float4 idx: cols 4j..4j+3
            const int s = j >> 2;
            const int cc = j & 3;
            const float4 f = *(const float4*)(wb + r * BW + j * 4);
            unsigned m0, m1, r0, r1;
            split_bf16_pair(f, m0, m1, r0, r1);
            const int nt = r >> 3;
            const int gg = r & 7;
            smB[((ii * 2 + s) * 4 + nt) * 32 + gg * 4 + cc] = make_uint4(m0, m1, r0, r1);
        }
        __syncthreads();

        // ---- rotated walk: warp (and CTA) dependent start index ----
        int li = (wid + (int)blockIdx.x) % n;
        for (int step = 0; step < n; ++step) {
            const float* xb = xw + g_col[rb][done + li] * BW;

            // A: 8 batched LDG.128 (MLP=8)
            float4 q[2][2][2];   // [mt][rowhalf a][s]
#pragma unroll
            for (int mt = 0; mt < 2; ++mt)
#pragma unroll
                for (int a = 0; a < 2; ++a)
#pragma unroll
                    for (int s = 0; s < 2; ++s)
                        q[mt][a][s] = *(const float4*)
                            (xb + (size_t)(mt * 16 + 8 * a + g) * IN_F + 16 * s + 4 * c);

#pragma unroll
            for (int s = 0; s < 2; ++s) {
                unsigned am[2][4], ar[2][4];
#pragma unroll
                for (int mt = 0; mt < 2; ++mt) {
                    split_bf16_pair(q[mt][0][s], am[mt][0], am[mt][2], ar[mt][0], ar[mt][2]);
                    split_bf16_pair(q[mt][1][s], am[mt][1], am[mt][3], ar[mt][1], ar[mt][3]);
                }
                uint4 bv[4];
#pragma unroll
                for (int nt = 0; nt < 4; ++nt)
                    bv[nt] = smB[((li * 2 + s) * 4 + nt) * 32 + lane];

                // term-major: RAW reuse distance 8
#pragma unroll
                for (int nt = 0; nt < 4; ++nt)
#pragma unroll
                    for (int mt = 0; mt < 2; ++mt)
                        mma_bf16(acc[mt][nt], am[mt], bv[nt].x, bv[nt].y);
#pragma unroll
                for (int nt = 0; nt < 4; ++nt)
#pragma unroll
                    for (int mt = 0; mt < 2; ++mt)
                        mma_bf16(acc[mt][nt], am[mt], bv[nt].z, bv[nt].w);
#pragma unroll
                for (int nt = 0; nt < 4; ++nt)
#pragma unroll
                    for (int mt = 0; mt < 2; ++mt)
                        mma_bf16(acc[mt][nt], ar[mt], bv[nt].x, bv[nt].y);
            }

            if (++li == n) li = 0;
        }
        done += n;
    }

    // ---- epilogue: add bias, store ----
    const float* bp = bias + rb * BH;
#pragma unroll
    for (int nt = 0; nt < 4; ++nt) {
        const float2 bv = *(const float2*)(bp + nt * 8 + 2 * c);
#pragma unroll
        for (int mt = 0; mt < 2; ++mt) {
            const int row0 = tok0 + wid * 32 + mt * 16 + g;
            float2 o0, o1;
            o0.x = acc[mt][nt][0] + bv.x;
            o0.y = acc[mt][nt][1] + bv.y;
            o1.x = acc[mt][nt][2] + bv.x;
            o1.y = acc[mt][nt][3] + bv.y;
            *(float2*)(out + (size_t)row0       * OUT_F + rb * BH + nt * 8 + 2 * c) = o0;
            *(float2*)(out + (size_t)(row0 + 8) * OUT_F + rb * BH + nt * 8 + 2 * c) = o1;
        }
    }
}

extern "C" void kernel_launch(void* const* d_in, const int* in_sizes, int n_in,
                              void* d_out, int out_size) {
    (void)in_sizes; (void)n_in; (void)out_size;
    const float* x    = (const float*)d_in[0];
    const float* w    = (const float*)d_in[1];
    const float* bias = (const float*)d_in[2];
    const int*   brow = (const int*)d_in[3];
    const int*   bcol = (const int*)d_in[4];
    float* out = (float*)d_out;

    spmm_prep_kernel<<<1, NB>>>(brow, bcol);
    dim3 grid(N_TOKENS / TOK_TILE, N_RB);
    spmm_main_kernel<<<grid, THREADS>>>(x, w, bias, out);
}